// round 5
// baseline (speedup 1.0000x reference)
#include <cuda_runtime.h>
#include <cuda_fp16.h>
#include <cstdint>

// Problem constants
#define N_TOK 262144
#define DIM   64
#define KCB   512
#define GAMMA 0.99f

#define TPB     256
#define TOK_CTA 256
#define NCTA    (N_TOK / TOK_CTA)
#define MARGIN  5e-4f    // >= ~15x worst-case fp16-split coarse error

// smem: codebook hi | mid (SW128-swizzled fp16) | bias fp32 | cn scratch
#define SM_B_HI   0
#define SM_B_MID  65536
#define SM_BIAS   131072
#define SMEM_BYTES (SM_BIAS + 4096)

#define SW(o) ((o) ^ (((o) >> 3) & 0x70))

// device globals (allocation-free; zero-init at load, self-rezeroing each call)
__device__ float g_cs[KCB * DIM];
__device__ float g_cn[KCB];
__device__ unsigned int g_done;

// ---------------- helpers ----------------
__device__ __forceinline__ uint32_t smem_u32(const void* p) {
    uint32_t a;
    asm("{ .reg .u64 t; cvta.to.shared.u64 t, %1; cvt.u32.u64 %0, t; }" : "=r"(a) : "l"(p));
    return a;
}
__device__ __forceinline__ void split2h(float a, float b, uint32_t& h, uint32_t& m) {
    __half2 hh = __floats2half2_rn(a, b);
    float2 bk = __half22float2(hh);
    __half2 mm = __floats2half2_rn(a - bk.x, b - bk.y);
    h = *reinterpret_cast<uint32_t*>(&hh);
    m = *reinterpret_cast<uint32_t*>(&mm);
}

#define LDMX4(R, A) \
    asm volatile("ldmatrix.sync.aligned.m8n8.x4.shared.b16 {%0,%1,%2,%3}, [%4];" \
                 : "=r"((R)[0]), "=r"((R)[1]), "=r"((R)[2]), "=r"((R)[3]) : "r"(A))

#define MMA(C, A, B0, B1) \
    asm volatile("mma.sync.aligned.m16n8k16.row.col.f32.f16.f16.f32 " \
                 "{%0,%1,%2,%3}, {%4,%5,%6,%7}, {%8,%9}, {%0,%1,%2,%3};" \
                 : "+f"((C)[0]), "+f"((C)[1]), "+f"((C)[2]), "+f"((C)[3]) \
                 : "r"((A)[0]), "r"((A)[1]), "r"((A)[2]), "r"((A)[3]), "r"(B0), "r"(B1))

__device__ __forceinline__ void upd(float v, int kk, float& best, float& second, int& bk) {
    if (v > best) { second = best; best = v; bk = kk; }
    else          { second = fmaxf(second, v); }
}

// rare path: exact fp32 rescan of all 512 codewords (kept out of hot regs)
__device__ __noinline__ int rescue(const float* __restrict__ x,
                                   const float* __restrict__ vq,
                                   const float* sbias, int tok) {
    float xr[DIM];
    const float4* xp = reinterpret_cast<const float4*>(x + (size_t)tok * DIM);
    #pragma unroll
    for (int i = 0; i < DIM / 4; i++) {
        float4 t = xp[i];
        xr[4 * i] = t.x; xr[4 * i + 1] = t.y; xr[4 * i + 2] = t.z; xr[4 * i + 3] = t.w;
    }
    float be = -3.4e38f;
    int bk = 0;
    #pragma unroll 1
    for (int k = 0; k < KCB; k++) {
        const float* vr = vq + (size_t)k * DIM;
        float a0 = 0.f, a1 = 0.f;
        #pragma unroll
        for (int d = 0; d < DIM; d += 2) {
            a0 = fmaf(xr[d],     __ldg(vr + d),     a0);
            a1 = fmaf(xr[d + 1], __ldg(vr + d + 1), a1);
        }
        float s = (a0 + a1) - sbias[k];
        if (s > be) { be = s; bk = k; }   // strict >: lowest k wins ties
    }
    return bk;
}

// ---------------- fused kernel ----------------
__global__ void __launch_bounds__(TPB, 1) vq_kernel(
    const float* __restrict__ x,
    const float* __restrict__ vq,
    const float* __restrict__ cs_in,
    const float* __restrict__ cn_in,
    float* __restrict__ q_out,
    float* __restrict__ vq_out,
    float* __restrict__ cs_out,
    float* __restrict__ cn_out)
{
    extern __shared__ __align__(1024) char smem[];
    float* sbias = reinterpret_cast<float*>(smem + SM_BIAS);
    const uint32_t sb = smem_u32(smem);
    const int tid = threadIdx.x;
    const int lane = tid & 31, wid = tid >> 5;
    const int g = lane >> 2, c = lane & 3;

    // ---- stage: split fp32 codebook -> fp16 hi/mid swizzled smem ----
    for (int i = tid; i < 4096; i += TPB) {           // 16B chunk i: row i>>3, cols (i&7)*8
        const float4* p = reinterpret_cast<const float4*>(vq + (i >> 3) * DIM + (i & 7) * 8);
        float4 v0 = __ldg(p), v1 = __ldg(p + 1);
        uint4 h4, m4;
        split2h(v0.x, v0.y, h4.x, m4.x);
        split2h(v0.z, v0.w, h4.y, m4.y);
        split2h(v1.x, v1.y, h4.z, m4.z);
        split2h(v1.z, v1.w, h4.w, m4.w);
        uint32_t off = SW((uint32_t)(i * 16));
        *reinterpret_cast<uint4*>(smem + SM_B_HI + off) = h4;
        *reinterpret_cast<uint4*>(smem + SM_B_MID + off) = m4;
    }
    // bias: 0.5*||v_k||^2 (exact fp32)
    for (int k = tid; k < KCB; k += TPB) {
        const float4* p = reinterpret_cast<const float4*>(vq + k * DIM);
        float s = 0.f;
        #pragma unroll
        for (int i = 0; i < DIM / 4; i++) {
            float4 t = __ldg(p + i);
            s += t.x * t.x + t.y * t.y + t.z * t.z + t.w * t.w;
        }
        sbias[k] = 0.5f * s;
    }

    // ---- A fragments: warp's 32 token rows x 64 dims, fp16 hi+mid ----
    uint32_t a_hi[2][4][4], a_mid[2][4][4];
    const int rowbase = blockIdx.x * TOK_CTA + wid * 32;
    #pragma unroll
    for (int m = 0; m < 2; m++) {
        #pragma unroll
        for (int kt = 0; kt < 4; kt++) {
            const float* p = x + (size_t)(rowbase + m * 16 + g) * DIM + kt * 16 + 2 * c;
            float2 f0 = *reinterpret_cast<const float2*>(p);
            float2 f1 = *reinterpret_cast<const float2*>(p + 8);
            float2 f2 = *reinterpret_cast<const float2*>(p + 8 * DIM);
            float2 f3 = *reinterpret_cast<const float2*>(p + 8 * DIM + 8);
            split2h(f0.x, f0.y, a_hi[m][kt][0], a_mid[m][kt][0]);
            split2h(f2.x, f2.y, a_hi[m][kt][1], a_mid[m][kt][1]);
            split2h(f1.x, f1.y, a_hi[m][kt][2], a_mid[m][kt][2]);
            split2h(f3.x, f3.y, a_hi[m][kt][3], a_mid[m][kt][3]);
        }
    }
    __syncthreads();

    float best[4]   = {-3.4e38f, -3.4e38f, -3.4e38f, -3.4e38f};
    float second[4] = {-3.4e38f, -3.4e38f, -3.4e38f, -3.4e38f};
    int   bk[4]     = {0, 0, 0, 0};

    #pragma unroll 1
    for (int n8 = 0; n8 < 64; n8 += 2) {
        const int n0 = n8 * 8;
        // 12 independent accumulator chains (3 split terms x 2 m x 2 n-halves)
        float Ahh[2][4] = {}, Ahm[2][4] = {}, Amh[2][4] = {};
        float Bhh[2][4] = {}, Bhm[2][4] = {}, Bmh[2][4] = {};
        #pragma unroll
        for (int kh = 0; kh < 2; kh++) {
            uint32_t kb = kh * 64 + ((lane >> 3) * 16);
            uint32_t offA = SW((uint32_t)((n0 + (lane & 7)) * 128) + kb);
            uint32_t offB = SW((uint32_t)((n0 + 8 + (lane & 7)) * 128) + kb);
            uint32_t bhA[4], bmA[4], bhB[4], bmB[4];
            LDMX4(bhA, sb + SM_B_HI + offA);
            LDMX4(bmA, sb + SM_B_MID + offA);
            LDMX4(bhB, sb + SM_B_HI + offB);
            LDMX4(bmB, sb + SM_B_MID + offB);
            #pragma unroll
            for (int kk = 0; kk < 2; kk++) {
                const int kt = kh * 2 + kk;
                #pragma unroll
                for (int m = 0; m < 2; m++) {
                    MMA(Ahh[m], a_hi[m][kt],  bhA[2 * kk], bhA[2 * kk + 1]);
                    MMA(Ahm[m], a_hi[m][kt],  bmA[2 * kk], bmA[2 * kk + 1]);
                    MMA(Amh[m], a_mid[m][kt], bhA[2 * kk], bhA[2 * kk + 1]);
                    MMA(Bhh[m], a_hi[m][kt],  bhB[2 * kk], bhB[2 * kk + 1]);
                    MMA(Bhm[m], a_hi[m][kt],  bmB[2 * kk], bmB[2 * kk + 1]);
                    MMA(Bmh[m], a_mid[m][kt], bhB[2 * kk], bhB[2 * kk + 1]);
                }
            }
        }
        const int kA = n0 + 2 * c, kB = n0 + 8 + 2 * c;
        float2 biasA = *reinterpret_cast<const float2*>(&sbias[kA]);
        float2 biasB = *reinterpret_cast<const float2*>(&sbias[kB]);
        #pragma unroll
        for (int m = 0; m < 2; m++) {
            float sA0 = Ahh[m][0] + Ahm[m][0] + Amh[m][0] - biasA.x;
            float sA1 = Ahh[m][1] + Ahm[m][1] + Amh[m][1] - biasA.y;
            float sA2 = Ahh[m][2] + Ahm[m][2] + Amh[m][2] - biasA.x;
            float sA3 = Ahh[m][3] + Ahm[m][3] + Amh[m][3] - biasA.y;
            float sB0 = Bhh[m][0] + Bhm[m][0] + Bmh[m][0] - biasB.x;
            float sB1 = Bhh[m][1] + Bhm[m][1] + Bmh[m][1] - biasB.y;
            float sB2 = Bhh[m][2] + Bhm[m][2] + Bmh[m][2] - biasB.x;
            float sB3 = Bhh[m][3] + Bhm[m][3] + Bmh[m][3] - biasB.y;
            upd(sA0, kA,     best[2 * m],     second[2 * m],     bk[2 * m]);
            upd(sA1, kA + 1, best[2 * m],     second[2 * m],     bk[2 * m]);
            upd(sA2, kA,     best[2 * m + 1], second[2 * m + 1], bk[2 * m + 1]);
            upd(sA3, kA + 1, best[2 * m + 1], second[2 * m + 1], bk[2 * m + 1]);
            upd(sB0, kB,     best[2 * m],     second[2 * m],     bk[2 * m]);
            upd(sB1, kB + 1, best[2 * m],     second[2 * m],     bk[2 * m]);
            upd(sB2, kB,     best[2 * m + 1], second[2 * m + 1], bk[2 * m + 1]);
            upd(sB3, kB + 1, best[2 * m + 1], second[2 * m + 1], bk[2 * m + 1]);
        }
    }

    // ---- quad merge (cols spread over c=0..3) ----
    #pragma unroll
    for (int mask = 1; mask <= 2; mask <<= 1) {
        #pragma unroll
        for (int s = 0; s < 4; s++) {
            float ob = __shfl_xor_sync(0xffffffffu, best[s], mask);
            float os = __shfl_xor_sync(0xffffffffu, second[s], mask);
            int   ok = __shfl_xor_sync(0xffffffffu, bk[s], mask);
            if (ob > best[s]) {
                second[s] = fmaxf(best[s], fmaxf(os, second[s]));
                best[s] = ob; bk[s] = ok;
            } else {
                second[s] = fmaxf(second[s], fmaxf(os, ob));
            }
        }
    }
    // redistribute: thread with lane L takes slot L>>3 from lane 4*(L&7)
    float myBest = 0.f, mySecond = 0.f;
    int myK = 0;
    #pragma unroll
    for (int s = 0; s < 4; s++) {
        float b  = __shfl_sync(0xffffffffu, best[s],   (lane & 7) * 4);
        float sc = __shfl_sync(0xffffffffu, second[s], (lane & 7) * 4);
        int   kk = __shfl_sync(0xffffffffu, bk[s],     (lane & 7) * 4);
        if ((lane >> 3) == s) { myBest = b; mySecond = sc; myK = kk; }
    }

    // ---- epilogue (thread t <-> token t) ----
    const int tok = blockIdx.x * TOK_CTA + tid;
    int best_k = myK;
    if (mySecond >= myBest - MARGIN)
        best_k = rescue(x, vq, sbias, tok);

    {   // quantized = vq[best_k]
        const float4* vr4 = reinterpret_cast<const float4*>(vq + (size_t)best_k * DIM);
        float4* q4 = reinterpret_cast<float4*>(q_out + (size_t)tok * DIM);
        #pragma unroll
        for (int i = 0; i < DIM / 4; i++) q4[i] = vr4[i];
    }
    {   // segment sums (RED)
        const float4* xp = reinterpret_cast<const float4*>(x + (size_t)tok * DIM);
        float* cs = g_cs + (size_t)best_k * DIM;
        #pragma unroll
        for (int i = 0; i < DIM / 4; i++) {
            float4 v = xp[i];
            atomicAdd(cs + 4 * i,     v.x);
            atomicAdd(cs + 4 * i + 1, v.y);
            atomicAdd(cs + 4 * i + 2, v.z);
            atomicAdd(cs + 4 * i + 3, v.w);
        }
        atomicAdd(&g_cn[best_k], 1.0f);
    }

    // ---- last CTA performs the EMA finalize ----
    __threadfence();
    __syncthreads();
    __shared__ int s_last;
    if (tid == 0) s_last = (atomicAdd(&g_done, 1u) == (unsigned)(gridDim.x - 1));
    __syncthreads();
    if (!s_last) return;
    __threadfence();   // acquire: all CTAs' REDs visible

    float* scn = sbias + KCB;   // reuse smem scratch for cn_new
    for (int k = tid; k < KCB; k += TPB) {
        float cn_acc = g_cn[k];
        g_cn[k] = 0.f;
        float cn_new = cn_in[k] * GAMMA + cn_acc * (1.0f - GAMMA);
        cn_out[k] = cn_new;
        scn[k] = cn_new;
    }
    __syncthreads();
    for (int idx = tid; idx < KCB * DIM; idx += TPB) {
        float cs_acc = g_cs[idx];
        g_cs[idx] = 0.f;
        float cs_new = cs_in[idx] * GAMMA + cs_acc * (1.0f - GAMMA);
        cs_out[idx] = cs_new;
        vq_out[idx] = cs_new / scn[idx >> 6];
    }
    if (tid == 0) g_done = 0u;   // reset for next graph replay
}

extern "C" void kernel_launch(void* const* d_in, const int* in_sizes, int n_in,
                              void* d_out, int out_size) {
    const float* x  = (const float*)d_in[0];   // [N, 64]
    const float* vq = (const float*)d_in[1];   // [512, 64]
    const float* cs = (const float*)d_in[2];   // [512, 64]
    const float* cn = (const float*)d_in[3];   // [512]

    float* out    = (float*)d_out;
    float* q_out  = out;                        // [N, 64]
    float* vq_out = out + (size_t)N_TOK * DIM;  // [512, 64]
    float* cs_out = vq_out + (size_t)KCB * DIM; // [512, 64]
    float* cn_out = cs_out + (size_t)KCB * DIM; // [512]

    cudaFuncSetAttribute(vq_kernel, cudaFuncAttributeMaxDynamicSharedMemorySize, SMEM_BYTES);
    vq_kernel<<<NCTA, TPB, SMEM_BYTES>>>(x, vq, cs, cn, q_out, vq_out, cs_out, cn_out);
}